// round 1
// baseline (speedup 1.0000x reference)
#include <cuda_runtime.h>
#include <cuda_bf16.h>
#include <math_constants.h>

#define MAX_ROWS 65536
#define BLK 256

__device__ float g_row_loss[MAX_ROWS];

__inline__ __device__ float warp_max(float v) {
    #pragma unroll
    for (int o = 16; o > 0; o >>= 1)
        v = fmaxf(v, __shfl_xor_sync(0xFFFFFFFFu, v, o));
    return v;
}

__inline__ __device__ float warp_sum(float v) {
    #pragma unroll
    for (int o = 16; o > 0; o >>= 1)
        v += __shfl_xor_sync(0xFFFFFFFFu, v, o);
    return v;
}

// One block per row. C <= 1024 (here C=1000 logits + 1 extra, row stride = C+1).
__global__ __launch_bounds__(BLK) void row_loss_kernel(
    const float* __restrict__ in, int C, float* __restrict__ row_loss)
{
    const int row = blockIdx.x;
    const float* __restrict__ p = in + (size_t)row * (size_t)(C + 1);
    const int t = threadIdx.x;
    const int wid = t >> 5;
    const int lane = t & 31;

    __shared__ float sh_max[BLK / 32];
    __shared__ float sh_se[BLK / 32];
    __shared__ float sh_sl[BLK / 32];

    const float extra = __ldg(p + C);   // broadcast load

    // Load row elements into registers (single pass over global memory)
    float v[4];
    float m = -CUDART_INF_F;
    #pragma unroll
    for (int k = 0; k < 4; k++) {
        const int j = t + k * BLK;
        v[k] = (j < C) ? __ldg(p + j) : -CUDART_INF_F;
        m = fmaxf(m, v[k]);
    }

    // Block-reduce max
    m = warp_max(m);
    if (lane == 0) sh_max[wid] = m;
    __syncthreads();
    float bm = sh_max[0];
    #pragma unroll
    for (int i = 1; i < BLK / 32; i++) bm = fmaxf(bm, sh_max[i]);

    // Sum of exp and sum of exp * log(sigmoid(extra - logit))
    float se = 0.0f, sl = 0.0f;
    #pragma unroll
    for (int k = 0; k < 4; k++) {
        const int j = t + k * BLK;
        if (j < C) {
            const float e = __expf(v[k] - bm);
            const float z = extra - v[k];
            // stable log(sigmoid(z)) = min(z,0) - log(1 + exp(-|z|))
            const float ls = fminf(z, 0.0f) - __logf(1.0f + __expf(-fabsf(z)));
            se += e;
            sl += e * ls;
        }
    }
    se = warp_sum(se);
    sl = warp_sum(sl);
    if (lane == 0) { sh_se[wid] = se; sh_sl[wid] = sl; }
    __syncthreads();

    if (t == 0) {
        float tse = 0.0f, tsl = 0.0f;
        #pragma unroll
        for (int i = 0; i < BLK / 32; i++) { tse += sh_se[i]; tsl += sh_sl[i]; }
        row_loss[row] = -tsl / tse;
    }
}

__global__ __launch_bounds__(1024) void final_reduce_kernel(
    const float* __restrict__ row_loss, int B, float* __restrict__ out)
{
    __shared__ float sh[32];
    const int t = threadIdx.x;
    float s = 0.0f;
    for (int i = t; i < B; i += 1024) s += row_loss[i];
    s = warp_sum(s);
    if ((t & 31) == 0) sh[t >> 5] = s;
    __syncthreads();
    if (t < 32) {
        float v = (t < 1024 / 32) ? sh[t] : 0.0f;
        v = warp_sum(v);
        if (t == 0) out[0] = v / (float)B;
    }
}

extern "C" void kernel_launch(void* const* d_in, const int* in_sizes, int n_in,
                              void* d_out, int out_size)
{
    const float* input = (const float*)d_in[0];
    const int B = in_sizes[1];                 // target has B elements
    const int C = in_sizes[0] / B - 1;         // logits per row (stride C+1)
    float* out = (float*)d_out;

    float* scratch;
    cudaGetSymbolAddress((void**)&scratch, g_row_loss);

    row_loss_kernel<<<B, BLK>>>(input, C, scratch);
    final_reduce_kernel<<<1, 1024>>>(scratch, B, out);
}

// round 6
// speedup vs baseline: 1.4899x; 1.4899x over previous
#include <cuda_runtime.h>
#include <cuda_bf16.h>

#define BLK 256
#define WARPS_PER_CTA 8
#define MAX_PARTIALS 8192

__device__ float g_partials[MAX_PARTIALS];
__device__ int   g_done = 0;

__inline__ __device__ float warp_sum(float v) {
    #pragma unroll
    for (int o = 16; o > 0; o >>= 1)
        v += __shfl_xor_sync(0xFFFFFFFFu, v, o);
    return v;
}

// One warp per row, streaming single pass:
//   E = exp(v);  log(sigmoid(extra - v)) = -log(1 + E*exp(-extra))
//   row_loss = (sum E*log(1+E*K)) / (sum E),  K = exp(-extra)
__global__ __launch_bounds__(BLK) void loss_kernel(
    const float* __restrict__ in, int C, int B, float* __restrict__ out)
{
    const int t    = threadIdx.x;
    const int lane = t & 31;
    const int wid  = t >> 5;
    const int row  = blockIdx.x * WARPS_PER_CTA + wid;

    __shared__ float sh_row[WARPS_PER_CTA];

    float se = 0.0f, sl = 0.0f;

    if (row < B) {
        const float* __restrict__ p = in + (size_t)row * (size_t)(C + 1);
        const float extra = __ldg(p + C);
        const float K = __expf(-extra);

        int base = 0;
        // 4-deep batched loads (uniform trip count across the warp)
        for (; base + 128 <= C; base += 128) {
            const float v0 = __ldg(p + base + lane);
            const float v1 = __ldg(p + base + lane + 32);
            const float v2 = __ldg(p + base + lane + 64);
            const float v3 = __ldg(p + base + lane + 96);
            const float e0 = __expf(v0), e1 = __expf(v1);
            const float e2 = __expf(v2), e3 = __expf(v3);
            const float l0 = __logf(fmaf(e0, K, 1.0f));
            const float l1 = __logf(fmaf(e1, K, 1.0f));
            const float l2 = __logf(fmaf(e2, K, 1.0f));
            const float l3 = __logf(fmaf(e3, K, 1.0f));
            se += (e0 + e1) + (e2 + e3);
            sl = fmaf(e0, l0, sl);
            sl = fmaf(e1, l1, sl);
            sl = fmaf(e2, l2, sl);
            sl = fmaf(e3, l3, sl);
        }
        for (; base + 32 <= C; base += 32) {
            const float v = __ldg(p + base + lane);
            const float e = __expf(v);
            const float l = __logf(fmaf(e, K, 1.0f));
            se += e;
            sl = fmaf(e, l, sl);
        }
        if (base + lane < C) {
            const float v = __ldg(p + base + lane);
            const float e = __expf(v);
            const float l = __logf(fmaf(e, K, 1.0f));
            se += e;
            sl = fmaf(e, l, sl);
        }
    }

    se = warp_sum(se);
    sl = warp_sum(sl);
    if (lane == 0)
        sh_row[wid] = (row < B) ? (sl / se) : 0.0f;   // positive row loss
    __syncthreads();

    // Per-CTA partial in a fixed order (deterministic)
    __shared__ bool is_last;
    if (t == 0) {
        float part = 0.0f;
        #pragma unroll
        for (int i = 0; i < WARPS_PER_CTA; i++) part += sh_row[i];
        g_partials[blockIdx.x] = part;
        __threadfence();
        is_last = (atomicAdd(&g_done, 1) == (int)gridDim.x - 1);
    }
    __syncthreads();

    // Last CTA reduces all partials in a fixed order
    if (is_last) {
        const int nP = gridDim.x;
        float s = 0.0f;
        for (int i = t; i < nP; i += BLK) s += g_partials[i];
        s = warp_sum(s);
        __shared__ float sh_fin[BLK / 32];
        if (lane == 0) sh_fin[t >> 5] = s;
        __syncthreads();
        if (t == 0) {
            float tot = 0.0f;
            #pragma unroll
            for (int i = 0; i < BLK / 32; i++) tot += sh_fin[i];
            out[0] = tot / (float)B;
            g_done = 0;   // reset for next graph replay
        }
    }
}

extern "C" void kernel_launch(void* const* d_in, const int* in_sizes, int n_in,
                              void* d_out, int out_size)
{
    const float* input = (const float*)d_in[0];
    const int B = in_sizes[1];             // target has B elements
    const int C = in_sizes[0] / B - 1;     // logits per row (stride C+1)
    float* out = (float*)d_out;

    const int grid = (B + WARPS_PER_CTA - 1) / WARPS_PER_CTA;  // 8192 for B=65536
    loss_kernel<<<grid, BLK>>>(input, C, B, out);
}

// round 7
// speedup vs baseline: 1.7207x; 1.1550x over previous
#include <cuda_runtime.h>
#include <cuda_bf16.h>

#define BLK 256
#define WPC 8
#define MAX_PARTIALS 8192

#define LOG2E 1.44269504088896340736f
#define LN2   0.69314718055994530942f

__device__ float g_partials[MAX_PARTIALS];
__device__ int   g_done = 0;

__device__ __forceinline__ float ex2f(float x) {
    float r; asm("ex2.approx.ftz.f32 %0, %1;" : "=f"(r) : "f"(x)); return r;
}
__device__ __forceinline__ float lg2f(float x) {
    float r; asm("lg2.approx.ftz.f32 %0, %1;" : "=f"(r) : "f"(x)); return r;
}

__inline__ __device__ float warp_sum(float v) {
    #pragma unroll
    for (int o = 16; o > 0; o >>= 1)
        v += __shfl_xor_sync(0xFFFFFFFFu, v, o);
    return v;
}

// One warp per row. Per element: e = 2^(v*log2e) (= exp v),
// l2 = log2(1 + e*K), K = exp(-extra). Row value = (Σ e*l2)/(Σ e);
// final loss = (Σ_rows rowval) * ln2 / B.
__global__ __launch_bounds__(BLK) void loss_kernel(
    const float* __restrict__ in, int C, int B, float* __restrict__ out)
{
    const int t    = threadIdx.x;
    const int lane = t & 31;
    const int wid  = t >> 5;
    const int row  = blockIdx.x * WPC + wid;

    __shared__ float sh_row[WPC];

    float se = 0.0f, sl = 0.0f;

    if (row < B) {
        const size_t S = (size_t)row * (size_t)(C + 1);   // row start (floats)
        const float extra = __ldg(in + S + C);
        const float K = ex2f(-extra * LOG2E);             // exp(-extra)

        const size_t A = (S + 3) & ~(size_t)3;            // 16B-aligned start
        const int head = (int)(A - S);                    // 0..3 scalar head elems

        if (lane < head) {
            const float v = __ldg(in + S + lane);
            const float e = ex2f(v * LOG2E);
            const float l2 = lg2f(fmaf(e, K, 1.0f));
            se += e;
            sl = fmaf(e, l2, sl);
        }

        const float4* __restrict__ fp4 = (const float4*)(in + A);
        const int body = (int)((size_t)(S + C) - A);      // floats in aligned body+tail
        const int n4   = body >> 2;
        const int tail = body & 3;
        const int nfull = n4 >> 5;                        // full 32-wide f4 iterations

        #pragma unroll 2
        for (int k = 0; k < nfull; k++) {
            const float4 q = __ldg(fp4 + (k << 5) + lane);
            const float e0 = ex2f(q.x * LOG2E);
            const float e1 = ex2f(q.y * LOG2E);
            const float e2 = ex2f(q.z * LOG2E);
            const float e3 = ex2f(q.w * LOG2E);
            const float l0 = lg2f(fmaf(e0, K, 1.0f));
            const float l1 = lg2f(fmaf(e1, K, 1.0f));
            const float l2 = lg2f(fmaf(e2, K, 1.0f));
            const float l3 = lg2f(fmaf(e3, K, 1.0f));
            se += (e0 + e1) + (e2 + e3);
            sl = fmaf(e0, l0, sl);
            sl = fmaf(e1, l1, sl);
            sl = fmaf(e2, l2, sl);
            sl = fmaf(e3, l3, sl);
        }
        {   // remainder float4s
            const int i = (nfull << 5) + lane;
            if (i < n4) {
                const float4 q = __ldg(fp4 + i);
                const float e0 = ex2f(q.x * LOG2E);
                const float e1 = ex2f(q.y * LOG2E);
                const float e2 = ex2f(q.z * LOG2E);
                const float e3 = ex2f(q.w * LOG2E);
                const float l0 = lg2f(fmaf(e0, K, 1.0f));
                const float l1 = lg2f(fmaf(e1, K, 1.0f));
                const float l2 = lg2f(fmaf(e2, K, 1.0f));
                const float l3 = lg2f(fmaf(e3, K, 1.0f));
                se += (e0 + e1) + (e2 + e3);
                sl = fmaf(e0, l0, sl);
                sl = fmaf(e1, l1, sl);
                sl = fmaf(e2, l2, sl);
                sl = fmaf(e3, l3, sl);
            }
        }
        if (lane < tail) {   // scalar tail
            const float v = __ldg(in + S + C - tail + lane);
            const float e = ex2f(v * LOG2E);
            const float l2 = lg2f(fmaf(e, K, 1.0f));
            se += e;
            sl = fmaf(e, l2, sl);
        }
    }

    se = warp_sum(se);
    sl = warp_sum(sl);
    if (lane == 0)
        sh_row[wid] = (row < B) ? (sl / se) : 0.0f;
    __syncthreads();

    __shared__ bool is_last;
    if (t == 0) {
        float part = 0.0f;
        #pragma unroll
        for (int i = 0; i < WPC; i++) part += sh_row[i];
        g_partials[blockIdx.x] = part;
        __threadfence();
        is_last = (atomicAdd(&g_done, 1) == (int)gridDim.x - 1);
    }
    __syncthreads();

    if (is_last) {
        const int nP = gridDim.x;
        float s = 0.0f;
        for (int i = t; i < nP; i += BLK) s += g_partials[i];
        s = warp_sum(s);
        __shared__ float sh_fin[BLK / 32];
        if (lane == 0) sh_fin[t >> 5] = s;
        __syncthreads();
        if (t == 0) {
            float tot = 0.0f;
            #pragma unroll
            for (int i = 0; i < BLK / 32; i++) tot += sh_fin[i];
            out[0] = tot * (LN2 / (float)B);
            g_done = 0;   // reset for next graph replay
        }
    }
}

extern "C" void kernel_launch(void* const* d_in, const int* in_sizes, int n_in,
                              void* d_out, int out_size)
{
    const float* input = (const float*)d_in[0];
    const int B = in_sizes[1];             // target has B elements
    const int C = in_sizes[0] / B - 1;     // logits per row (row stride C+1)
    float* out = (float*)d_out;

    const int grid = (B + WPC - 1) / WPC;  // 8192 for B=65536
    loss_kernel<<<grid, BLK>>>(input, C, B, out);
}